// round 14
// baseline (speedup 1.0000x reference)
#include <cuda_runtime.h>
#include <cuda_fp16.h>
#include <cstdint>

#define DSPAN 1024
#define HID   128
#define FEAT  20
#define NWID  30
#define MARGIN 8192u

// ======================= device scratch =======================
__device__ int      g_h8a[256];
__device__ int      g_h8b[256];
__device__ unsigned g_lou, g_hiu;
__device__ int      g_nband, g_cabove;
__device__ unsigned g_thru;
__device__ int      g_cut;
__device__ int      g_bcnt[256];
__device__ int      g_boff[256];
__device__ int      g_scnt, g_sflag;
__device__ int      g_hcnt, g_hflag;
__device__ int      g_topi[4096];
__device__ float    g_width[32];
__device__ int      g_band[65536];
// W1 transposed [H][D] fp16
__device__ __align__(16) __half g_w1t[HID * DSPAN];

__device__ __forceinline__ unsigned f2u(float f) {
    unsigned b = __float_as_uint(f);
    return b ^ ((unsigned)((int)b >> 31) | 0x80000000u);
}
__device__ __forceinline__ bool sel_pred(unsigned u, int i, unsigned thr, int cut) {
    return (u > thr) || (u == thr && i <= cut);
}
__device__ __forceinline__ uint32_t smem_u32(const void* p) {
    uint32_t a;
    asm("{ .reg .u64 t; cvta.to.shared.u64 t, %1; cvt.u32.u64 %0, t; }" : "=r"(a) : "l"(p));
    return a;
}
__device__ __forceinline__ void ldm_x4(uint32_t& r0, uint32_t& r1, uint32_t& r2, uint32_t& r3, uint32_t a) {
    asm volatile("ldmatrix.sync.aligned.m8n8.x4.shared.b16 {%0,%1,%2,%3}, [%4];"
                 : "=r"(r0), "=r"(r1), "=r"(r2), "=r"(r3) : "r"(a));
}
__device__ __forceinline__ void mma_f16(float* d, const uint32_t* a, uint32_t b0, uint32_t b1) {
    asm volatile(
        "mma.sync.aligned.m16n8k16.row.col.f32.f16.f16.f32 "
        "{%0,%1,%2,%3}, {%4,%5,%6,%7}, {%8,%9}, {%0,%1,%2,%3};"
        : "+f"(d[0]), "+f"(d[1]), "+f"(d[2]), "+f"(d[3])
        : "r"(a[0]), "r"(a[1]), "r"(a[2]), "r"(a[3]), "r"(b0), "r"(b1));
}
__device__ __forceinline__ unsigned pack_h2(__half a, __half b) {
    return (unsigned)__half_as_ushort(a) | ((unsigned)__half_as_ushort(b) << 16);
}
__device__ __forceinline__ void cp_async16(uint32_t dst, const void* src) {
    asm volatile("cp.async.cg.shared.global [%0], [%1], 16;" :: "r"(dst), "l"(src));
}

// block-wide locate over a 256-bin histogram (suffix sums)
__device__ __forceinline__ void locate256(const int* __restrict__ hist, int K,
                                          int* ps, int* sb, int* sneed, int t) {
    if (t < 256) ps[t] = hist[t];
    __syncthreads();
    #pragma unroll
    for (int off = 1; off < 256; off <<= 1) {
        int v = (t < 256 && t + off < 256) ? ps[t + off] : 0;
        __syncthreads();
        if (t < 256) ps[t] += v;
        __syncthreads();
    }
    if (t < 256) {
        int nxt = (t == 255) ? 0 : ps[t + 1];
        if (ps[t] >= K && nxt < K) { *sb = t; *sneed = K - nxt; }
    }
    __syncthreads();
}

// ======================= prep: zero | W1 cvt | width prior (parallel) =======================
__global__ void k_prep(const float* __restrict__ W1,
                       const float* __restrict__ emb,
                       const float* __restrict__ Ww1, const float* __restrict__ bw1,
                       const float* __restrict__ Ww2, const float* __restrict__ bw2) {
    int bid = blockIdx.x, tid = threadIdx.x;
    if (bid == 0) {
        if (tid < 256) { g_h8a[tid] = 0; g_h8b[tid] = 0; }
        if (tid == 0) { g_nband = 0; g_cabove = 0; g_scnt = 0; g_sflag = 0; g_hcnt = 0; g_hflag = 0; }
    } else if (bid <= 512) {
        int o = (bid - 1) * 256 + tid;     // 0..131071
        int kk = o >> 7, n = o & 127;
        g_w1t[n * DSPAN + kk] = __float2half_rn(W1[o]);
    } else {
        int w = bid - 513;                 // 0..NWID-1
        __shared__ float red[128];
        int j = tid;
        if (j < 128) {
            float acc = bw1[j];
            #pragma unroll
            for (int kk = 0; kk < FEAT; kk++)
                acc += emb[w * FEAT + kk] * Ww1[kk * HID + j];
            red[j] = fmaxf(acc, 0.f) * Ww2[j];
        }
        __syncthreads();
        for (int s = 64; s > 0; s >>= 1) {
            if (j < s) red[j] += red[j + s];
            __syncthreads();
        }
        if (j == 0) g_width[w] = red[0] + bw2[0];
    }
}

// ======================= fp16 warp-MMA GEMM: 64-row CTAs, 4/SM (R10/R11, proven) =======================
#define SA 40
#define A_TILE_H (64 * SA)
#define B_TILE_H (128 * SA)
__global__ __launch_bounds__(128, 4)
void k_gemm(const float* __restrict__ x,
            const float* __restrict__ b1, const float* __restrict__ W2,
            const float* __restrict__ b2, const int* __restrict__ widx,
            float* __restrict__ scores, int N) {
    __shared__ __align__(16) __half sA[2][A_TILE_H];
    __shared__ __align__(16) __half sB[2][B_TILE_H];
    __shared__ float sb1[128], sw2[128];
    __shared__ float sred[2][64];
    __shared__ int hh[256];

    int tid = threadIdx.x;
    int wid = tid >> 5, lid = tid & 31;
    int warp_m = wid & 1, warp_n = wid >> 1;
    int wm = warp_m * 32, wn = warp_n * 64;
    int gid = lid >> 2, tig = lid & 3;
    int m0 = blockIdx.x * 64;

    sb1[tid] = b1[tid]; sw2[tid] = W2[tid];
    hh[tid] = 0; hh[tid + 128] = 0;

    float acc[2][8][4];
    #pragma unroll
    for (int mt = 0; mt < 2; mt++)
        #pragma unroll
        for (int nt = 0; nt < 8; nt++)
            #pragma unroll
            for (int q = 0; q < 4; q++) acc[mt][nt][q] = 0.f;

    const float* xblk = x + (size_t)m0 * DSPAN;
    uint32_t uA0 = smem_u32(sA[0]), uA1 = smem_u32(sA[1]);
    uint32_t uB0 = smem_u32(sB[0]), uB1 = smem_u32(sB[1]);

    int a_ld_row = tid >> 3, a_ld_c4 = tid & 7;
    int b_ld_row = tid >> 2, b_ld_seg = tid & 3;

    int a_row = (lid & 15);
    int a_kk  = (lid >> 4) << 3;
    int b_row = (lid & 7) + ((lid & 16) ? 8 : 0);
    int b_kk  = (lid & 8);

    float4 aR[4];

    auto ldg_a = [&](int ch) {
        int kt = ch * 32;
        #pragma unroll
        for (int p = 0; p < 4; p++) {
            int row = a_ld_row + p * 16;
            aR[p] = *reinterpret_cast<const float4*>(xblk + (size_t)row * DSPAN + kt + a_ld_c4 * 4);
        }
    };
    auto cpasync_b = [&](int ch, uint32_t uB) {
        int kt = ch * 32;
        #pragma unroll
        for (int p = 0; p < 4; p++) {
            int row = b_ld_row + p * 32;
            const void* src = &g_w1t[(size_t)row * DSPAN + kt + b_ld_seg * 8];
            cp_async16(uB + (uint32_t)(row * SA + b_ld_seg * 8) * 2, src);
        }
        asm volatile("cp.async.commit_group;");
    };
    auto sts_a = [&](__half* dstA) {
        #pragma unroll
        for (int p = 0; p < 4; p++) {
            int row = a_ld_row + p * 16;
            float4 v = aR[p];
            unsigned u0 = pack_h2(__float2half_rn(v.x), __float2half_rn(v.y));
            unsigned u1 = pack_h2(__float2half_rn(v.z), __float2half_rn(v.w));
            *reinterpret_cast<uint2*>(&dstA[row * SA + a_ld_c4 * 4]) = make_uint2(u0, u1);
        }
    };

    ldg_a(0);
    cpasync_b(0, uB0);
    sts_a(sA[0]);
    asm volatile("cp.async.wait_group 0;");
    __syncthreads();

    int buf = 0;
    for (int ch = 0; ch < 32; ch++) {
        uint32_t uA = buf ? uA1 : uA0;
        uint32_t uB = buf ? uB1 : uB0;
        if (ch < 31) {
            ldg_a(ch + 1);
            cpasync_b(ch + 1, buf ? uB0 : uB1);
        }

        #pragma unroll
        for (int s = 0; s < 2; s++) {
            uint32_t ah[2][4];
            #pragma unroll
            for (int mt = 0; mt < 2; mt++) {
                uint32_t aoff = (uint32_t)(((wm + mt * 16 + a_row) * SA + s * 16 + a_kk) * 2);
                ldm_x4(ah[mt][0], ah[mt][1], ah[mt][2], ah[mt][3], uA + aoff);
            }
            #pragma unroll
            for (int np = 0; np < 4; np++) {
                uint32_t boff = (uint32_t)(((wn + np * 16 + b_row) * SA + s * 16 + b_kk) * 2);
                uint32_t b0, b1v, b2v, b3;
                ldm_x4(b0, b1v, b2v, b3, uB + boff);
                #pragma unroll
                for (int mt = 0; mt < 2; mt++) {
                    mma_f16(acc[mt][np * 2],     ah[mt], b0, b1v);
                    mma_f16(acc[mt][np * 2 + 1], ah[mt], b2v, b3);
                }
            }
        }

        if (ch < 31) {
            sts_a(buf ? sA[0] : sA[1]);
            asm volatile("cp.async.wait_group 0;");
        }
        __syncthreads();
        buf ^= 1;
    }

    #pragma unroll
    for (int mt = 0; mt < 2; mt++) {
        #pragma unroll
        for (int h = 0; h < 2; h++) {
            float s = 0.f;
            #pragma unroll
            for (int nt = 0; nt < 8; nt++) {
                int col = wn + nt * 8 + tig * 2;
                float v0 = acc[mt][nt][h * 2 + 0] + sb1[col];
                float v1 = acc[mt][nt][h * 2 + 1] + sb1[col + 1];
                s += fmaxf(v0, 0.f) * sw2[col] + fmaxf(v1, 0.f) * sw2[col + 1];
            }
            s += __shfl_xor_sync(0xFFFFFFFFu, s, 1);
            s += __shfl_xor_sync(0xFFFFFFFFu, s, 2);
            if (tig == 0) sred[warp_n][wm + mt * 16 + h * 8 + gid] = s;
        }
    }
    __syncthreads();
    if (tid < 64) {
        int row = m0 + tid;
        if (row < N) {
            float sc = sred[0][tid] + sred[1][tid] + __ldg(b2) + g_width[widx[row]];
            scores[row] = sc;
            atomicAdd(&hh[f2u(sc) >> 24], 1);
        }
    }
    __syncthreads();
    if (hh[tid]) atomicAdd(&g_h8a[tid], hh[tid]);
    if (hh[tid + 128]) atomicAdd(&g_h8a[tid + 128], hh[tid + 128]);
}

// ======================= fused: pass-2 histogram + grid-sync + band/count =======================
__global__ void k_h8bc(const float* __restrict__ scores, int N, int K) {
    __shared__ int ps[256];
    __shared__ int sb, sneed;
    __shared__ int h[8][256];
    __shared__ int red[8];
    int t = threadIdx.x, w = t >> 5;

    locate256(g_h8a, K, ps, &sb, &sneed, t);
    int bhi = sb, needA = sneed;
    __syncthreads();

    for (int b = t; b < 2048; b += 256) ((int*)h)[b] = 0;
    __syncthreads();

    int i = blockIdx.x * 1024 + t * 4;
    if (i + 3 < N) {
        float4 v = *reinterpret_cast<const float4*>(scores + i);
        unsigned u0 = f2u(v.x), u1 = f2u(v.y), u2 = f2u(v.z), u3 = f2u(v.w);
        if ((int)(u0 >> 24) == bhi) atomicAdd(&h[w][(u0 >> 16) & 0xFF], 1);
        if ((int)(u1 >> 24) == bhi) atomicAdd(&h[w][(u1 >> 16) & 0xFF], 1);
        if ((int)(u2 >> 24) == bhi) atomicAdd(&h[w][(u2 >> 16) & 0xFF], 1);
        if ((int)(u3 >> 24) == bhi) atomicAdd(&h[w][(u3 >> 16) & 0xFF], 1);
    } else {
        for (int e = 0; e < 4; e++) {
            int j = i + e;
            if (j < N) {
                unsigned u = f2u(scores[j]);
                if ((int)(u >> 24) == bhi) atomicAdd(&h[w][(u >> 16) & 0xFF], 1);
            }
        }
    }
    __syncthreads();
    for (int b = t; b < 256; b += 256) {
        int s = 0;
        #pragma unroll
        for (int ww = 0; ww < 8; ww++) s += h[ww][b];
        if (s) atomicAdd(&g_h8b[b], s);
    }

    __threadfence();
    __syncthreads();
    if (t == 0) {
        if (atomicAdd(&g_hcnt, 1) == (int)gridDim.x - 1) atomicExch(&g_hflag, 1);
        while (atomicAdd(&g_hflag, 0) == 0) {}
    }
    __syncthreads();
    __threadfence();

    locate256(g_h8b, needA, ps, &sb, &sneed, t);
    int b2 = sb;

    unsigned base = (((unsigned)bhi << 8) | (unsigned)b2) << 16;
    unsigned top = base | 0xFFFFu;
    unsigned lo = (base >= MARGIN) ? base - MARGIN : 0u;
    unsigned hi = (top <= 0xFFFFFFFFu - MARGIN) ? top + MARGIN : 0xFFFFFFFFu;
    if (blockIdx.x == 0 && t == 0) { g_lou = lo; g_hiu = hi; }

    int c = 0;
    #pragma unroll
    for (int e = 0; e < 4; e++) {
        int j = i + e;
        if (j < N) {
            unsigned u = f2u(scores[j]);
            if (u > hi) c++;
            else if (u >= lo) {
                int p = atomicAdd(&g_nband, 1);
                if (p < 65536) g_band[p] = j;
            }
        }
    }
    for (int off = 16; off > 0; off >>= 1) c += __shfl_down_sync(0xFFFFFFFFu, c, off);
    if ((t & 31) == 0) red[t >> 5] = c;
    __syncthreads();
    if (t < 8) {
        int v = red[t];
        for (int off = 4; off > 0; off >>= 1) v += __shfl_down_sync(0xFFu, v, off);
        if (t == 0 && v) atomicAdd(&g_cabove, v);
    }
}

// ---- exact fp32 recompute of band rows: 8 rows/block, MLP-8 inner loop ----
__global__ void k_exact(const float* __restrict__ x,
                        const float* __restrict__ W1, const float* __restrict__ b1,
                        const float* __restrict__ W2, const float* __restrict__ b2,
                        const int* __restrict__ widx, float* __restrict__ scores) {
    __shared__ float xs[8][1024];
    __shared__ float red[8][128];
    int nb = min(g_nband, 65536);
    unsigned hiu = g_hiu;
    int j = threadIdx.x;   // 128 threads
    for (int base = blockIdx.x * 8; base < nb; base += gridDim.x * 8) {
        int m = min(8, nb - base);
        for (int r = 0; r < 8; r++) {
            if (r < m) {
                const float* src = x + (size_t)g_band[base + r] * DSPAN;
                for (int t = j; t < 1024; t += 128) xs[r][t] = src[t];
            } else {
                for (int t = j; t < 1024; t += 128) xs[r][t] = 0.f;
            }
        }
        __syncthreads();
        float a[8];
        #pragma unroll
        for (int r = 0; r < 8; r++) a[r] = b1[j];
        #pragma unroll 8
        for (int kk = 0; kk < 1024; kk++) {
            float w = W1[kk * HID + j];
            #pragma unroll
            for (int r = 0; r < 8; r++) a[r] += xs[r][kk] * w;
        }
        float w2 = W2[j];
        #pragma unroll
        for (int r = 0; r < 8; r++) red[r][j] = fmaxf(a[r], 0.f) * w2;
        __syncthreads();
        for (int s = 64; s > 0; s >>= 1) {
            if (j < s) {
                #pragma unroll
                for (int r = 0; r < 8; r++) red[r][j] += red[r][j + s];
            }
            __syncthreads();
        }
        if (j == 0) {
            for (int r = 0; r < m; r++) {
                int i = g_band[base + r];
                float v = red[r][0] + b2[0] + g_width[widx[i]];
                scores[i] = v;
                if (f2u(v) > hiu) atomicAdd(&g_cabove, 1);
            }
        }
        __syncthreads();
    }
}

// ---- rank-select the threshold among band members (single block) ----
__global__ void k_bandrank(const float* __restrict__ scores, int K) {
    __shared__ unsigned long long keys[4096];
    int m = min(g_nband, 4096);
    int need = K - g_cabove;
    unsigned hiu = g_hiu;
    for (int i = threadIdx.x; i < m; i += blockDim.x) {
        int idx = g_band[i];
        unsigned u = f2u(scores[idx]);
        keys[i] = (u > hiu) ? 0ULL
                : (((unsigned long long)u << 32) | (unsigned)(~(unsigned)idx));
    }
    __syncthreads();
    for (int i = threadIdx.x; i < m; i += blockDim.x) {
        unsigned long long ki = keys[i];
        if (ki == 0ULL) continue;
        int r = 0;
        for (int j = 0; j < m; j++) r += (keys[j] > ki) ? 1 : 0;
        if (r == need - 1) {
            g_thru = (unsigned)(ki >> 32);
            g_cut = (int)(~(unsigned)ki);
        }
    }
}

// ======================= fused count + scan + scatter (last-block pattern) =======================
__global__ void k_scatter(const float* __restrict__ scores,
                          const int* __restrict__ beg, const int* __restrict__ end, int N,
                          float* __restrict__ o_ti, float* __restrict__ o_sc,
                          float* __restrict__ o_bg, float* __restrict__ o_en) {
    __shared__ int s[1024];
    __shared__ int sarr[256];
    __shared__ int slast, sboff;
    int t = threadIdx.x, bid = blockIdx.x;
    unsigned thr = g_thru;
    int cut = g_cut;
    int base = bid * 4096 + t * 4;
    bool f[4];
    int c = 0;
    #pragma unroll
    for (int e = 0; e < 4; e++) {
        int i = base + e;
        f[e] = (i < N) && sel_pred(f2u(scores[i]), i, thr, cut);
        c += f[e] ? 1 : 0;
    }
    s[t] = c;
    __syncthreads();
    for (int off = 1; off < 1024; off <<= 1) {
        int add = (t >= off) ? s[t - off] : 0;
        __syncthreads();
        s[t] += add;
        __syncthreads();
    }
    if (t == 0) {
        g_bcnt[bid] = s[1023];
        __threadfence();
        slast = (atomicAdd(&g_scnt, 1) == (int)gridDim.x - 1) ? 1 : 0;
    }
    __syncthreads();
    if (slast) {
        if (t < (int)gridDim.x) sarr[t] = g_bcnt[t];
        __syncthreads();
        if (t == 0) {
            int run = 0;
            for (int b = 0; b < (int)gridDim.x; b++) { g_boff[b] = run; run += sarr[b]; }
            __threadfence();
            atomicExch(&g_sflag, 1);
        }
    }
    if (t == 0) {
        while (atomicAdd(&g_sflag, 0) == 0) {}
        __threadfence();
        sboff = g_boff[bid];
    }
    __syncthreads();
    int pos = sboff + s[t] - c;
    #pragma unroll
    for (int e = 0; e < 4; e++) {
        if (f[e]) {
            int i = base + e;
            g_topi[pos] = i;
            o_ti[pos] = (float)i;
            o_sc[pos] = scores[i];
            o_bg[pos] = (float)beg[i];
            o_en[pos] = (float)end[i];
            pos++;
        }
    }
}

__global__ void k_gather(const float* __restrict__ x, float* __restrict__ out) {
    int r = blockIdx.x;
    int src = g_topi[r];
    const float4* s = reinterpret_cast<const float4*>(x + (size_t)src * DSPAN);
    float4* d = reinterpret_cast<float4*>(out + (size_t)r * DSPAN);
    d[threadIdx.x] = s[threadIdx.x];
}

// ======================= launch =======================
extern "C" void kernel_launch(void* const* d_in, const int* in_sizes, int n_in,
                              void* d_out, int out_size) {
    const float* x    = (const float*)d_in[0];
    const int*   cbeg = (const int*)d_in[1];
    const int*   cend = (const int*)d_in[2];
    const int*   cwid = (const int*)d_in[3];
    const float* wemb = (const float*)d_in[4];
    const float* W1   = (const float*)d_in[5];
    const float* b1   = (const float*)d_in[6];
    const float* W2   = (const float*)d_in[7];
    const float* b2   = (const float*)d_in[8];
    const float* Ww1  = (const float*)d_in[9];
    const float* bw1  = (const float*)d_in[10];
    const float* Ww2  = (const float*)d_in[11];
    const float* bw2  = (const float*)d_in[12];

    int N = in_sizes[1];                 // 262144
    int D = in_sizes[0] / N;             // 1024
    int k = (out_size - N) / (D + 4);    // 3276

    float* out     = (float*)d_out;
    float* o_prune = out;                        // [N]
    float* o_vecs  = out + N;                    // [k, D]
    float* o_sc    = o_vecs + (size_t)k * D;     // [k]
    float* o_bg    = o_sc + k;                   // [k]
    float* o_en    = o_bg + k;                   // [k]
    float* o_ti    = o_en + k;                   // [k]

    k_prep<<<513 + NWID, 256>>>(W1, wemb, Ww1, bw1, Ww2, bw2);

    k_gemm<<<N / 64, 128>>>(x, b1, W2, b2, cwid, o_prune, N);

    int nb4 = (N + 1023) / 1024;         // 256
    k_h8bc<<<nb4, 256>>>(o_prune, N, k);
    k_exact<<<512, 128>>>(x, W1, b1, W2, b2, cwid, o_prune);
    k_bandrank<<<1, 1024>>>(o_prune, k);

    int nb = (N + 4095) / 4096;          // 64
    k_scatter<<<nb, 1024>>>(o_prune, cbeg, cend, N, o_ti, o_sc, o_bg, o_en);

    k_gather<<<k, 256>>>(x, o_vecs);
}

// round 15
// speedup vs baseline: 1.4964x; 1.4964x over previous
#include <cuda_runtime.h>
#include <cuda_fp16.h>
#include <cstdint>

#define DSPAN 1024
#define HID   128
#define FEAT  20
#define NWID  30
#define MARGIN 8192u

// ======================= device scratch =======================
__device__ int      g_h8a[256];
__device__ int      g_h8b[256];
__device__ unsigned g_lou, g_hiu;
__device__ int      g_nband, g_cabove;
__device__ unsigned g_thru;
__device__ int      g_cut;
__device__ int      g_bcnt[256];
__device__ int      g_boff[256];
__device__ int      g_scnt, g_sflag;
__device__ int      g_hcnt, g_hflag;
__device__ int      g_topi[4096];
__device__ float    g_width[32];
__device__ int      g_band[65536];
// W1 transposed [H][D] fp16
__device__ __align__(16) __half g_w1t[HID * DSPAN];

__device__ __forceinline__ unsigned f2u(float f) {
    unsigned b = __float_as_uint(f);
    return b ^ ((unsigned)((int)b >> 31) | 0x80000000u);
}
__device__ __forceinline__ bool sel_pred(unsigned u, int i, unsigned thr, int cut) {
    return (u > thr) || (u == thr && i <= cut);
}
__device__ __forceinline__ uint32_t smem_u32(const void* p) {
    uint32_t a;
    asm("{ .reg .u64 t; cvta.to.shared.u64 t, %1; cvt.u32.u64 %0, t; }" : "=r"(a) : "l"(p));
    return a;
}
__device__ __forceinline__ void ldm_x4(uint32_t& r0, uint32_t& r1, uint32_t& r2, uint32_t& r3, uint32_t a) {
    asm volatile("ldmatrix.sync.aligned.m8n8.x4.shared.b16 {%0,%1,%2,%3}, [%4];"
                 : "=r"(r0), "=r"(r1), "=r"(r2), "=r"(r3) : "r"(a));
}
__device__ __forceinline__ void mma_f16(float* d, const uint32_t* a, uint32_t b0, uint32_t b1) {
    asm volatile(
        "mma.sync.aligned.m16n8k16.row.col.f32.f16.f16.f32 "
        "{%0,%1,%2,%3}, {%4,%5,%6,%7}, {%8,%9}, {%0,%1,%2,%3};"
        : "+f"(d[0]), "+f"(d[1]), "+f"(d[2]), "+f"(d[3])
        : "r"(a[0]), "r"(a[1]), "r"(a[2]), "r"(a[3]), "r"(b0), "r"(b1));
}
__device__ __forceinline__ unsigned pack_h2(__half a, __half b) {
    return (unsigned)__half_as_ushort(a) | ((unsigned)__half_as_ushort(b) << 16);
}
__device__ __forceinline__ void cp_async16(uint32_t dst, const void* src) {
    asm volatile("cp.async.cg.shared.global [%0], [%1], 16;" :: "r"(dst), "l"(src));
}

// block-wide locate over a 256-bin histogram (suffix sums)
__device__ __forceinline__ void locate256(const int* __restrict__ hist, int K,
                                          int* ps, int* sb, int* sneed, int t) {
    if (t < 256) ps[t] = hist[t];
    __syncthreads();
    #pragma unroll
    for (int off = 1; off < 256; off <<= 1) {
        int v = (t < 256 && t + off < 256) ? ps[t + off] : 0;
        __syncthreads();
        if (t < 256) ps[t] += v;
        __syncthreads();
    }
    if (t < 256) {
        int nxt = (t == 255) ? 0 : ps[t + 1];
        if (ps[t] >= K && nxt < K) { *sb = t; *sneed = K - nxt; }
    }
    __syncthreads();
}

// ======================= prep: zero | W1 cvt | width prior (parallel) =======================
__global__ void k_prep(const float* __restrict__ W1,
                       const float* __restrict__ emb,
                       const float* __restrict__ Ww1, const float* __restrict__ bw1,
                       const float* __restrict__ Ww2, const float* __restrict__ bw2) {
    int bid = blockIdx.x, tid = threadIdx.x;
    if (bid == 0) {
        if (tid < 256) { g_h8a[tid] = 0; g_h8b[tid] = 0; }
        if (tid == 0) { g_nband = 0; g_cabove = 0; g_scnt = 0; g_sflag = 0; g_hcnt = 0; g_hflag = 0; }
    } else if (bid <= 512) {
        int o = (bid - 1) * 256 + tid;     // 0..131071
        int kk = o >> 7, n = o & 127;
        g_w1t[n * DSPAN + kk] = __float2half_rn(W1[o]);
    } else {
        int w = bid - 513;                 // 0..NWID-1
        __shared__ float red[128];
        int j = tid;
        if (j < 128) {
            float acc = bw1[j];
            #pragma unroll
            for (int kk = 0; kk < FEAT; kk++)
                acc += emb[w * FEAT + kk] * Ww1[kk * HID + j];
            red[j] = fmaxf(acc, 0.f) * Ww2[j];
        }
        __syncthreads();
        for (int s = 64; s > 0; s >>= 1) {
            if (j < s) red[j] += red[j + s];
            __syncthreads();
        }
        if (j == 0) g_width[w] = red[0] + bw2[0];
    }
}

// ======================= fp16 warp-MMA GEMM: 64-row CTAs, 4/SM (R10/R11, proven) =======================
#define SA 40
#define A_TILE_H (64 * SA)
#define B_TILE_H (128 * SA)
__global__ __launch_bounds__(128, 4)
void k_gemm(const float* __restrict__ x,
            const float* __restrict__ b1, const float* __restrict__ W2,
            const float* __restrict__ b2, const int* __restrict__ widx,
            float* __restrict__ scores, int N) {
    __shared__ __align__(16) __half sA[2][A_TILE_H];
    __shared__ __align__(16) __half sB[2][B_TILE_H];
    __shared__ float sb1[128], sw2[128];
    __shared__ float sred[2][64];
    __shared__ int hh[256];

    int tid = threadIdx.x;
    int wid = tid >> 5, lid = tid & 31;
    int warp_m = wid & 1, warp_n = wid >> 1;
    int wm = warp_m * 32, wn = warp_n * 64;
    int gid = lid >> 2, tig = lid & 3;
    int m0 = blockIdx.x * 64;

    sb1[tid] = b1[tid]; sw2[tid] = W2[tid];
    hh[tid] = 0; hh[tid + 128] = 0;

    float acc[2][8][4];
    #pragma unroll
    for (int mt = 0; mt < 2; mt++)
        #pragma unroll
        for (int nt = 0; nt < 8; nt++)
            #pragma unroll
            for (int q = 0; q < 4; q++) acc[mt][nt][q] = 0.f;

    const float* xblk = x + (size_t)m0 * DSPAN;
    uint32_t uA0 = smem_u32(sA[0]), uA1 = smem_u32(sA[1]);
    uint32_t uB0 = smem_u32(sB[0]), uB1 = smem_u32(sB[1]);

    int a_ld_row = tid >> 3, a_ld_c4 = tid & 7;
    int b_ld_row = tid >> 2, b_ld_seg = tid & 3;

    int a_row = (lid & 15);
    int a_kk  = (lid >> 4) << 3;
    int b_row = (lid & 7) + ((lid & 16) ? 8 : 0);
    int b_kk  = (lid & 8);

    float4 aR[4];

    auto ldg_a = [&](int ch) {
        int kt = ch * 32;
        #pragma unroll
        for (int p = 0; p < 4; p++) {
            int row = a_ld_row + p * 16;
            aR[p] = *reinterpret_cast<const float4*>(xblk + (size_t)row * DSPAN + kt + a_ld_c4 * 4);
        }
    };
    auto cpasync_b = [&](int ch, uint32_t uB) {
        int kt = ch * 32;
        #pragma unroll
        for (int p = 0; p < 4; p++) {
            int row = b_ld_row + p * 32;
            const void* src = &g_w1t[(size_t)row * DSPAN + kt + b_ld_seg * 8];
            cp_async16(uB + (uint32_t)(row * SA + b_ld_seg * 8) * 2, src);
        }
        asm volatile("cp.async.commit_group;");
    };
    auto sts_a = [&](__half* dstA) {
        #pragma unroll
        for (int p = 0; p < 4; p++) {
            int row = a_ld_row + p * 16;
            float4 v = aR[p];
            unsigned u0 = pack_h2(__float2half_rn(v.x), __float2half_rn(v.y));
            unsigned u1 = pack_h2(__float2half_rn(v.z), __float2half_rn(v.w));
            *reinterpret_cast<uint2*>(&dstA[row * SA + a_ld_c4 * 4]) = make_uint2(u0, u1);
        }
    };

    ldg_a(0);
    cpasync_b(0, uB0);
    sts_a(sA[0]);
    asm volatile("cp.async.wait_group 0;");
    __syncthreads();

    int buf = 0;
    for (int ch = 0; ch < 32; ch++) {
        uint32_t uA = buf ? uA1 : uA0;
        uint32_t uB = buf ? uB1 : uB0;
        if (ch < 31) {
            ldg_a(ch + 1);
            cpasync_b(ch + 1, buf ? uB0 : uB1);
        }

        #pragma unroll
        for (int s = 0; s < 2; s++) {
            uint32_t ah[2][4];
            #pragma unroll
            for (int mt = 0; mt < 2; mt++) {
                uint32_t aoff = (uint32_t)(((wm + mt * 16 + a_row) * SA + s * 16 + a_kk) * 2);
                ldm_x4(ah[mt][0], ah[mt][1], ah[mt][2], ah[mt][3], uA + aoff);
            }
            #pragma unroll
            for (int np = 0; np < 4; np++) {
                uint32_t boff = (uint32_t)(((wn + np * 16 + b_row) * SA + s * 16 + b_kk) * 2);
                uint32_t b0, b1v, b2v, b3;
                ldm_x4(b0, b1v, b2v, b3, uB + boff);
                #pragma unroll
                for (int mt = 0; mt < 2; mt++) {
                    mma_f16(acc[mt][np * 2],     ah[mt], b0, b1v);
                    mma_f16(acc[mt][np * 2 + 1], ah[mt], b2v, b3);
                }
            }
        }

        if (ch < 31) {
            sts_a(buf ? sA[0] : sA[1]);
            asm volatile("cp.async.wait_group 0;");
        }
        __syncthreads();
        buf ^= 1;
    }

    #pragma unroll
    for (int mt = 0; mt < 2; mt++) {
        #pragma unroll
        for (int h = 0; h < 2; h++) {
            float s = 0.f;
            #pragma unroll
            for (int nt = 0; nt < 8; nt++) {
                int col = wn + nt * 8 + tig * 2;
                float v0 = acc[mt][nt][h * 2 + 0] + sb1[col];
                float v1 = acc[mt][nt][h * 2 + 1] + sb1[col + 1];
                s += fmaxf(v0, 0.f) * sw2[col] + fmaxf(v1, 0.f) * sw2[col + 1];
            }
            s += __shfl_xor_sync(0xFFFFFFFFu, s, 1);
            s += __shfl_xor_sync(0xFFFFFFFFu, s, 2);
            if (tig == 0) sred[warp_n][wm + mt * 16 + h * 8 + gid] = s;
        }
    }
    __syncthreads();
    if (tid < 64) {
        int row = m0 + tid;
        if (row < N) {
            float sc = sred[0][tid] + sred[1][tid] + __ldg(b2) + g_width[widx[row]];
            scores[row] = sc;
            atomicAdd(&hh[f2u(sc) >> 24], 1);
        }
    }
    __syncthreads();
    if (hh[tid]) atomicAdd(&g_h8a[tid], hh[tid]);
    if (hh[tid + 128]) atomicAdd(&g_h8a[tid + 128], hh[tid + 128]);
}

// ======================= fused: pass-2 histogram + grid-sync + band/count =======================
__global__ void k_h8bc(const float* __restrict__ scores, int N, int K) {
    __shared__ int ps[256];
    __shared__ int sb, sneed;
    __shared__ int h[8][256];
    __shared__ int red[8];
    int t = threadIdx.x, w = t >> 5;

    locate256(g_h8a, K, ps, &sb, &sneed, t);
    int bhi = sb, needA = sneed;
    __syncthreads();

    for (int b = t; b < 2048; b += 256) ((int*)h)[b] = 0;
    __syncthreads();

    int i = blockIdx.x * 1024 + t * 4;
    if (i + 3 < N) {
        float4 v = *reinterpret_cast<const float4*>(scores + i);
        unsigned u0 = f2u(v.x), u1 = f2u(v.y), u2 = f2u(v.z), u3 = f2u(v.w);
        if ((int)(u0 >> 24) == bhi) atomicAdd(&h[w][(u0 >> 16) & 0xFF], 1);
        if ((int)(u1 >> 24) == bhi) atomicAdd(&h[w][(u1 >> 16) & 0xFF], 1);
        if ((int)(u2 >> 24) == bhi) atomicAdd(&h[w][(u2 >> 16) & 0xFF], 1);
        if ((int)(u3 >> 24) == bhi) atomicAdd(&h[w][(u3 >> 16) & 0xFF], 1);
    } else {
        for (int e = 0; e < 4; e++) {
            int j = i + e;
            if (j < N) {
                unsigned u = f2u(scores[j]);
                if ((int)(u >> 24) == bhi) atomicAdd(&h[w][(u >> 16) & 0xFF], 1);
            }
        }
    }
    __syncthreads();
    for (int b = t; b < 256; b += 256) {
        int s = 0;
        #pragma unroll
        for (int ww = 0; ww < 8; ww++) s += h[ww][b];
        if (s) atomicAdd(&g_h8b[b], s);
    }

    __threadfence();
    __syncthreads();
    if (t == 0) {
        if (atomicAdd(&g_hcnt, 1) == (int)gridDim.x - 1) atomicExch(&g_hflag, 1);
        while (atomicAdd(&g_hflag, 0) == 0) {}
    }
    __syncthreads();
    __threadfence();

    locate256(g_h8b, needA, ps, &sb, &sneed, t);
    int b2 = sb;

    unsigned base = (((unsigned)bhi << 8) | (unsigned)b2) << 16;
    unsigned top = base | 0xFFFFu;
    unsigned lo = (base >= MARGIN) ? base - MARGIN : 0u;
    unsigned hi = (top <= 0xFFFFFFFFu - MARGIN) ? top + MARGIN : 0xFFFFFFFFu;
    if (blockIdx.x == 0 && t == 0) { g_lou = lo; g_hiu = hi; }

    int c = 0;
    #pragma unroll
    for (int e = 0; e < 4; e++) {
        int j = i + e;
        if (j < N) {
            unsigned u = f2u(scores[j]);
            if (u > hi) c++;
            else if (u >= lo) {
                int p = atomicAdd(&g_nband, 1);
                if (p < 65536) g_band[p] = j;
            }
        }
    }
    for (int off = 16; off > 0; off >>= 1) c += __shfl_down_sync(0xFFFFFFFFu, c, off);
    if ((t & 31) == 0) red[t >> 5] = c;
    __syncthreads();
    if (t < 8) {
        int v = red[t];
        for (int off = 4; off > 0; off >>= 1) v += __shfl_down_sync(0xFFu, v, off);
        if (t == 0 && v) atomicAdd(&g_cabove, v);
    }
}

// ---- exact fp32 recompute: ONE row per block, k-split across 1024 threads ----
// Serial W1 chain per thread: 128 loads (vs 1024) -> latency-bound time ~8x lower.
__global__ void k_exact(const float* __restrict__ x,
                        const float* __restrict__ W1, const float* __restrict__ b1,
                        const float* __restrict__ W2, const float* __restrict__ b2,
                        const int* __restrict__ widx, float* __restrict__ scores) {
    __shared__ float xs[1024];
    __shared__ float part[8][128];
    int nb = min(g_nband, 65536);
    unsigned hiu = g_hiu;
    int t = threadIdx.x;               // 0..1023
    int j = t & 127, ks = t >> 7;      // hidden j, k-slice ks (8 slices of 128)
    for (int r = blockIdx.x; r < nb; r += gridDim.x) {
        int i = g_band[r];
        xs[t] = x[(size_t)i * DSPAN + t];
        __syncthreads();
        const float* wp = W1 + (size_t)(ks * 128) * HID + j;
        const float* xp = xs + ks * 128;
        float acc = 0.f;
        #pragma unroll 4
        for (int q = 0; q < 128; q++) acc += xp[q] * wp[(size_t)q * HID];
        part[ks][j] = acc;
        __syncthreads();
        if (t < 128) {
            float hsum = b1[j];
            #pragma unroll
            for (int s = 0; s < 8; s++) hsum += part[s][j];
            part[0][j] = fmaxf(hsum, 0.f) * W2[j];
        }
        __syncthreads();
        for (int s = 64; s > 0; s >>= 1) {
            if (t < s) part[0][t] += part[0][t + s];
            __syncthreads();
        }
        if (t == 0) {
            float v = part[0][0] + b2[0] + g_width[widx[i]];
            scores[i] = v;
            if (f2u(v) > hiu) atomicAdd(&g_cabove, 1);
        }
        __syncthreads();
    }
}

// ---- rank-select the threshold among band members (single block) ----
__global__ void k_bandrank(const float* __restrict__ scores, int K) {
    __shared__ unsigned long long keys[4096];
    int m = min(g_nband, 4096);
    int need = K - g_cabove;
    unsigned hiu = g_hiu;
    for (int i = threadIdx.x; i < m; i += blockDim.x) {
        int idx = g_band[i];
        unsigned u = f2u(scores[idx]);
        keys[i] = (u > hiu) ? 0ULL
                : (((unsigned long long)u << 32) | (unsigned)(~(unsigned)idx));
    }
    __syncthreads();
    for (int i = threadIdx.x; i < m; i += blockDim.x) {
        unsigned long long ki = keys[i];
        if (ki == 0ULL) continue;
        int r = 0;
        for (int j = 0; j < m; j++) r += (keys[j] > ki) ? 1 : 0;
        if (r == need - 1) {
            g_thru = (unsigned)(ki >> 32);
            g_cut = (int)(~(unsigned)ki);
        }
    }
}

// ======================= fused count + scan + scatter (last-block pattern) =======================
__global__ void k_scatter(const float* __restrict__ scores,
                          const int* __restrict__ beg, const int* __restrict__ end, int N,
                          float* __restrict__ o_ti, float* __restrict__ o_sc,
                          float* __restrict__ o_bg, float* __restrict__ o_en) {
    __shared__ int s[1024];
    __shared__ int sarr[256];
    __shared__ int slast, sboff;
    int t = threadIdx.x, bid = blockIdx.x;
    unsigned thr = g_thru;
    int cut = g_cut;
    int base = bid * 4096 + t * 4;
    bool f[4];
    int c = 0;
    #pragma unroll
    for (int e = 0; e < 4; e++) {
        int i = base + e;
        f[e] = (i < N) && sel_pred(f2u(scores[i]), i, thr, cut);
        c += f[e] ? 1 : 0;
    }
    s[t] = c;
    __syncthreads();
    for (int off = 1; off < 1024; off <<= 1) {
        int add = (t >= off) ? s[t - off] : 0;
        __syncthreads();
        s[t] += add;
        __syncthreads();
    }
    if (t == 0) {
        g_bcnt[bid] = s[1023];
        __threadfence();
        slast = (atomicAdd(&g_scnt, 1) == (int)gridDim.x - 1) ? 1 : 0;
    }
    __syncthreads();
    if (slast) {
        if (t < (int)gridDim.x) sarr[t] = g_bcnt[t];
        __syncthreads();
        if (t == 0) {
            int run = 0;
            for (int b = 0; b < (int)gridDim.x; b++) { g_boff[b] = run; run += sarr[b]; }
            __threadfence();
            atomicExch(&g_sflag, 1);
        }
    }
    if (t == 0) {
        while (atomicAdd(&g_sflag, 0) == 0) {}
        __threadfence();
        sboff = g_boff[bid];
    }
    __syncthreads();
    int pos = sboff + s[t] - c;
    #pragma unroll
    for (int e = 0; e < 4; e++) {
        if (f[e]) {
            int i = base + e;
            g_topi[pos] = i;
            o_ti[pos] = (float)i;
            o_sc[pos] = scores[i];
            o_bg[pos] = (float)beg[i];
            o_en[pos] = (float)end[i];
            pos++;
        }
    }
}

__global__ void k_gather(const float* __restrict__ x, float* __restrict__ out) {
    int r = blockIdx.x;
    int src = g_topi[r];
    const float4* s = reinterpret_cast<const float4*>(x + (size_t)src * DSPAN);
    float4* d = reinterpret_cast<float4*>(out + (size_t)r * DSPAN);
    d[threadIdx.x] = s[threadIdx.x];
}

// ======================= launch =======================
extern "C" void kernel_launch(void* const* d_in, const int* in_sizes, int n_in,
                              void* d_out, int out_size) {
    const float* x    = (const float*)d_in[0];
    const int*   cbeg = (const int*)d_in[1];
    const int*   cend = (const int*)d_in[2];
    const int*   cwid = (const int*)d_in[3];
    const float* wemb = (const float*)d_in[4];
    const float* W1   = (const float*)d_in[5];
    const float* b1   = (const float*)d_in[6];
    const float* W2   = (const float*)d_in[7];
    const float* b2   = (const float*)d_in[8];
    const float* Ww1  = (const float*)d_in[9];
    const float* bw1  = (const float*)d_in[10];
    const float* Ww2  = (const float*)d_in[11];
    const float* bw2  = (const float*)d_in[12];

    int N = in_sizes[1];                 // 262144
    int D = in_sizes[0] / N;             // 1024
    int k = (out_size - N) / (D + 4);    // 3276

    float* out     = (float*)d_out;
    float* o_prune = out;                        // [N]
    float* o_vecs  = out + N;                    // [k, D]
    float* o_sc    = o_vecs + (size_t)k * D;     // [k]
    float* o_bg    = o_sc + k;                   // [k]
    float* o_en    = o_bg + k;                   // [k]
    float* o_ti    = o_en + k;                   // [k]

    k_prep<<<513 + NWID, 256>>>(W1, wemb, Ww1, bw1, Ww2, bw2);

    k_gemm<<<N / 64, 128>>>(x, b1, W2, b2, cwid, o_prune, N);

    int nb4 = (N + 1023) / 1024;         // 256
    k_h8bc<<<nb4, 256>>>(o_prune, N, k);
    k_exact<<<512, 1024>>>(x, W1, b1, W2, b2, cwid, o_prune);
    k_bandrank<<<1, 1024>>>(o_prune, k);

    int nb = (N + 4095) / 4096;          // 64
    k_scatter<<<nb, 1024>>>(o_prune, cbeg, cend, N, o_ti, o_sc, o_bg, o_en);

    k_gather<<<k, 256>>>(x, o_vecs);
}